// round 4
// baseline (speedup 1.0000x reference)
#include <cuda_runtime.h>
#include <math.h>

#define Bsz 8
#define Cdim 256
#define HW 2304
#define CHW (Cdim*HW)          // 589824
#define BNEPS 1e-5f
#define INV_C (1.0f/256.0f)

// ---- static scratch (allocation-free) ----
__device__ float g_QL[Bsz*CHW];
__device__ float g_QR[Bsz*CHW];
__device__ float g_KL[Bsz*CHW];
__device__ float g_KR[Bsz*CHW];
__device__ float g_WfQ[Cdim*Cdim];
__device__ float g_WfK[Cdim*Cdim];
__device__ float g_bfQ[Cdim];
__device__ float g_bfK[Cdim];

// ============================================================
// Fold BN into conv1x1:  y = (W s) x + ((b - m) s + beta),  s = g*rsqrt(v+eps)
// ============================================================
__global__ void fold_kernel(const float* __restrict__ Wq, const float* __restrict__ bq,
                            const float* __restrict__ gq, const float* __restrict__ betaq,
                            const float* __restrict__ mq, const float* __restrict__ vq,
                            const float* __restrict__ Wk, const float* __restrict__ bk,
                            const float* __restrict__ gk, const float* __restrict__ betak,
                            const float* __restrict__ mk, const float* __restrict__ vk)
{
    int idx = blockIdx.x * blockDim.x + threadIdx.x;
    if (idx >= Cdim * Cdim) return;
    int o = idx >> 8;
    float sq = gq[o] * rsqrtf(vq[o] + BNEPS);
    float sk = gk[o] * rsqrtf(vk[o] + BNEPS);
    g_WfQ[idx] = Wq[idx] * sq;
    g_WfK[idx] = Wk[idx] * sk;
    if ((idx & 255) == 0) {
        g_bfQ[o] = (bq[o] - mq[o]) * sq + betaq[o];
        g_bfK[o] = (bk[o] - mk[o]) * sk + betak[o];
    }
}

// ============================================================
// Projection GEMM: out[o, n] = sum_c Wf[o, c] * X[c, n] + bf[o]
// M=256(o) x N=2304(n) x K=256(c), per (proj, batch).
// Block: 64x64 tile, 256 threads, 4x4 micro-tile, BK=16.
// blockIdx: x = n-tile (36), y = o-tile (4), z = p*8 + b (32)
//   p: 0=(Q,left)->g_QL, 1=(Q,right)->g_QR, 2=(K,left)->g_KL, 3=(K,right)->g_KR
// ============================================================
__global__ void proj_kernel(const float* __restrict__ fleft, const float* __restrict__ fright)
{
    int z = blockIdx.z;
    int p = z >> 3;
    int b = z & 7;
    const float* X  = ((p & 1) ? fright : fleft) + b * CHW;
    const float* Wf = (p < 2) ? g_WfQ : g_WfK;
    const float* bf = (p < 2) ? g_bfQ : g_bfK;
    float* dst = (p == 0) ? g_QL : (p == 1) ? g_QR : (p == 2) ? g_KL : g_KR;
    dst += b * CHW;

    __shared__ __align__(16) float Wt[16][68];   // Wt[c][o] (transposed)
    __shared__ __align__(16) float Xs[16][64];   // Xs[c][n]

    int tid = threadIdx.x;
    int tx = tid & 15, ty = tid >> 4;
    int o0 = blockIdx.y * 64, n0 = blockIdx.x * 64;

    float acc[4][4] = {};

    for (int k0 = 0; k0 < 256; k0 += 16) {
        __syncthreads();
        // load W tile 64(o) x 16(c), transpose into Wt[c][o]
        #pragma unroll
        for (int l = 0; l < 4; l++) {
            int idx = tid + l * 256;
            int o = idx >> 4, c = idx & 15;
            Wt[c][o] = Wf[(o0 + o) * 256 + k0 + c];
        }
        // load X tile 16(c) x 64(n)
        {
            int c = tid >> 4, n4 = tid & 15;
            float4 v = *(const float4*)&X[(k0 + c) * HW + n0 + n4 * 4];
            *(float4*)&Xs[c][n4 * 4] = v;
        }
        __syncthreads();
        #pragma unroll
        for (int c = 0; c < 16; c++) {
            float4 av = *(const float4*)&Wt[c][ty * 4];
            float4 bv = *(const float4*)&Xs[c][tx * 4];
            float aa[4] = {av.x, av.y, av.z, av.w};
            float bb[4] = {bv.x, bv.y, bv.z, bv.w};
            #pragma unroll
            for (int i = 0; i < 4; i++)
                #pragma unroll
                for (int j = 0; j < 4; j++)
                    acc[i][j] += aa[i] * bb[j];
        }
    }

    #pragma unroll
    for (int i = 0; i < 4; i++) {
        float bias = bf[o0 + ty * 4 + i];
        float4 ov;
        ov.x = acc[i][0] + bias;
        ov.y = acc[i][1] + bias;
        ov.z = acc[i][2] + bias;
        ov.w = acc[i][3] + bias;
        *(float4*)&dst[(o0 + ty * 4 + i) * HW + n0 + tx * 4] = ov;
    }
}

// ============================================================
// Fused flash attention (fp32).
// Q, K, V are (2304 x 256) row-major reinterpretations of (C,H,W) flat buffers.
// S = Q K^T / 256; A = softmax(S); Out[col*HW + row] = (A V)[row][col]  (transposed write)
// Block: 64 query rows; iterate 36 key tiles of 64. 256 threads (16x16),
// 4x4 S micro-tile, O owned as rows(4) x [4 dchunks x 4 cols].
// blockIdx: x = q-tile (36), y = unit (16: att*8 + b)
// ============================================================
__global__ void attn_kernel(const float* __restrict__ fleft, const float* __restrict__ fright,
                            float* __restrict__ out)
{
    extern __shared__ float sm[];
    float* Qst = sm;                 // [256][64]  Qst[d][r]
    float* Kst = Qst + 256 * 64;     // [256][64]  Kst[d][c]
    float* Vs  = Kst + 256 * 64;     // [64][256]  Vs[k][d]
    float* Pst = Vs + 64 * 256;      // [64][68]   Pst[c][r]

    int u = blockIdx.y;
    int att = u >> 3;
    int b = u & 7;
    const float* Q = (att == 0 ? g_QL : g_QR) + b * CHW;
    const float* K = (att == 0 ? g_KR : g_KL) + b * CHW;
    const float* V = (att == 0 ? fright : fleft) + b * CHW;
    float* O = out + att * (Bsz * CHW) + b * CHW;

    int q0 = blockIdx.x * 64;
    int tid = threadIdx.x;
    int tx = tid & 15, ty = tid >> 4;

    // load Q tile transposed: Qst[d][r] = Q[(q0+r)*256 + d]
    #pragma unroll
    for (int l = 0; l < 16; l++) {
        int idx = tid + l * 256;
        int d4 = idx >> 6, r = idx & 63;
        float4 v = *(const float4*)&Q[(q0 + r) * 256 + d4 * 4];
        Qst[(d4 * 4 + 0) * 64 + r] = v.x;
        Qst[(d4 * 4 + 1) * 64 + r] = v.y;
        Qst[(d4 * 4 + 2) * 64 + r] = v.z;
        Qst[(d4 * 4 + 3) * 64 + r] = v.w;
    }

    float Oacc[4][16];   // [row i][dchunk jc * 4 + j]
    #pragma unroll
    for (int i = 0; i < 4; i++)
        #pragma unroll
        for (int j = 0; j < 16; j++) Oacc[i][j] = 0.0f;
    float mi[4] = {-1e30f, -1e30f, -1e30f, -1e30f};
    float li[4] = {0.0f, 0.0f, 0.0f, 0.0f};

    for (int kt = 0; kt < 36; kt++) {
        int k0 = kt * 64;
        __syncthreads();
        // load K tile transposed: Kst[d][c] = K[(k0+c)*256 + d]
        #pragma unroll
        for (int l = 0; l < 16; l++) {
            int idx = tid + l * 256;
            int d4 = idx >> 6, c = idx & 63;
            float4 v = *(const float4*)&K[(k0 + c) * 256 + d4 * 4];
            Kst[(d4 * 4 + 0) * 64 + c] = v.x;
            Kst[(d4 * 4 + 1) * 64 + c] = v.y;
            Kst[(d4 * 4 + 2) * 64 + c] = v.z;
            Kst[(d4 * 4 + 3) * 64 + c] = v.w;
        }
        // load V tile direct: Vs[k][d]  (64 k-rows x 256 d = 4096 float4)
        #pragma unroll
        for (int l = 0; l < 16; l++) {
            int idx = tid + l * 256;
            int k = idx >> 6, d4 = idx & 63;
            *(float4*)&Vs[k * 256 + d4 * 4] = *(const float4*)&V[(k0 + k) * 256 + d4 * 4];
        }
        __syncthreads();

        // S tile: S[r][c] = sum_d Q[r][d] * K[c][d]
        float S[4][4] = {};
        #pragma unroll 8
        for (int d = 0; d < 256; d++) {
            float4 av = *(const float4*)&Qst[d * 64 + ty * 4];
            float4 bv = *(const float4*)&Kst[d * 64 + tx * 4];
            float aa[4] = {av.x, av.y, av.z, av.w};
            float bb[4] = {bv.x, bv.y, bv.z, bv.w};
            #pragma unroll
            for (int i = 0; i < 4; i++)
                #pragma unroll
                for (int j = 0; j < 4; j++)
                    S[i][j] += aa[i] * bb[j];
        }

        // online softmax update
        float P[4][4];
        #pragma unroll
        for (int i = 0; i < 4; i++) {
            float mrow = -1e30f;
            #pragma unroll
            for (int j = 0; j < 4; j++) {
                S[i][j] *= INV_C;
                mrow = fmaxf(mrow, S[i][j]);
            }
            #pragma unroll
            for (int off = 1; off < 16; off <<= 1)
                mrow = fmaxf(mrow, __shfl_xor_sync(0xFFFFFFFFu, mrow, off));
            float mnew = fmaxf(mi[i], mrow);
            float alpha = __expf(mi[i] - mnew);
            float rs = 0.0f;
            #pragma unroll
            for (int j = 0; j < 4; j++) {
                P[i][j] = __expf(S[i][j] - mnew);
                rs += P[i][j];
            }
            #pragma unroll
            for (int off = 1; off < 16; off <<= 1)
                rs += __shfl_xor_sync(0xFFFFFFFFu, rs, off);
            li[i] = li[i] * alpha + rs;
            mi[i] = mnew;
            #pragma unroll
            for (int j = 0; j < 16; j++) Oacc[i][j] *= alpha;
        }

        // write P transposed: Pst[c][r] = P[r][c]
        #pragma unroll
        for (int j = 0; j < 4; j++) {
            int c = tx * 4 + j;
            float4 pv;
            pv.x = P[0][j]; pv.y = P[1][j]; pv.z = P[2][j]; pv.w = P[3][j];
            *(float4*)&Pst[c * 68 + ty * 4] = pv;
        }
        __syncthreads();

        // O += P @ V
        #pragma unroll 2
        for (int k = 0; k < 64; k++) {
            float4 av = *(const float4*)&Pst[k * 68 + ty * 4];
            float pa[4] = {av.x, av.y, av.z, av.w};
            #pragma unroll
            for (int jc = 0; jc < 4; jc++) {
                float4 vv = *(const float4*)&Vs[k * 256 + jc * 64 + tx * 4];
                float vb[4] = {vv.x, vv.y, vv.z, vv.w};
                #pragma unroll
                for (int i = 0; i < 4; i++)
                    #pragma unroll
                    for (int j = 0; j < 4; j++)
                        Oacc[i][jc * 4 + j] += pa[i] * vb[j];
            }
        }
    }

    // epilogue: normalize and write transposed (contiguous in row index n)
    float rl[4];
    #pragma unroll
    for (int i = 0; i < 4; i++) rl[i] = 1.0f / li[i];
    #pragma unroll
    for (int jc = 0; jc < 4; jc++) {
        #pragma unroll
        for (int j = 0; j < 4; j++) {
            int col = jc * 64 + tx * 4 + j;
            float4 ov;
            ov.x = Oacc[0][jc * 4 + j] * rl[0];
            ov.y = Oacc[1][jc * 4 + j] * rl[1];
            ov.z = Oacc[2][jc * 4 + j] * rl[2];
            ov.w = Oacc[3][jc * 4 + j] * rl[3];
            *(float4*)&O[col * HW + q0 + ty * 4] = ov;
        }
    }
}

#define ATTN_SMEM ((256*64 + 256*64 + 64*256 + 64*68) * (int)sizeof(float))

extern "C" void kernel_launch(void* const* d_in, const int* in_sizes, int n_in,
                              void* d_out, int out_size)
{
    const float* fea_left  = (const float*)d_in[0];
    const float* fea_right = (const float*)d_in[1];
    const float* Wq    = (const float*)d_in[2];
    const float* bq    = (const float*)d_in[3];
    const float* gq    = (const float*)d_in[4];
    const float* betaq = (const float*)d_in[5];
    const float* mq    = (const float*)d_in[6];
    const float* vq    = (const float*)d_in[7];
    const float* Wk    = (const float*)d_in[8];
    const float* bk    = (const float*)d_in[9];
    const float* gk    = (const float*)d_in[10];
    const float* betak = (const float*)d_in[11];
    const float* mk    = (const float*)d_in[12];
    const float* vk    = (const float*)d_in[13];
    float* out = (float*)d_out;

    fold_kernel<<<256, 256>>>(Wq, bq, gq, betaq, mq, vq, Wk, bk, gk, betak, mk, vk);
    proj_kernel<<<dim3(36, 4, 32), 256>>>(fea_left, fea_right);

    cudaFuncSetAttribute(attn_kernel, cudaFuncAttributeMaxDynamicSharedMemorySize, ATTN_SMEM);
    attn_kernel<<<dim3(36, 16), 256, ATTN_SMEM>>>(fea_left, fea_right, out);
}

// round 6
// speedup vs baseline: 5.0478x; 5.0478x over previous
#include <cuda_runtime.h>
#include <cuda_bf16.h>
#include <cstdint>
#include <math.h>

#define Bsz 8
#define Cdim 256
#define HW 2304
#define CHW (Cdim*HW)          // 589824
#define BNEPS 1e-5f
#define INV_C (1.0f/256.0f)

// ---- static scratch (allocation-free) ----
__device__ float g_QL[Bsz*CHW];
__device__ float g_QR[Bsz*CHW];
__device__ float g_KL[Bsz*CHW];
__device__ float g_KR[Bsz*CHW];
__device__ float g_WfQ[Cdim*Cdim];
__device__ float g_WfK[Cdim*Cdim];
__device__ float g_bfQ[Cdim];
__device__ float g_bfK[Cdim];

// ============================================================
// helpers
// ============================================================
__device__ __forceinline__ uint32_t smem_u32(const void* p) {
    uint32_t a;
    asm("{ .reg .u64 t; cvta.to.shared.u64 t, %1; cvt.u32.u64 %0, t; }" : "=r"(a) : "l"(p));
    return a;
}
__device__ __forceinline__ void ldsm_x4(uint32_t a, uint32_t& r0, uint32_t& r1, uint32_t& r2, uint32_t& r3) {
    asm volatile("ldmatrix.sync.aligned.m8n8.x4.shared.b16 {%0,%1,%2,%3}, [%4];"
                 : "=r"(r0), "=r"(r1), "=r"(r2), "=r"(r3) : "r"(a));
}
__device__ __forceinline__ void ldsm_x2(uint32_t a, uint32_t& r0, uint32_t& r1) {
    asm volatile("ldmatrix.sync.aligned.m8n8.x2.shared.b16 {%0,%1}, [%2];"
                 : "=r"(r0), "=r"(r1) : "r"(a));
}
__device__ __forceinline__ void ldsm_x2t(uint32_t a, uint32_t& r0, uint32_t& r1) {
    asm volatile("ldmatrix.sync.aligned.m8n8.x2.trans.shared.b16 {%0,%1}, [%2];"
                 : "=r"(r0), "=r"(r1) : "r"(a));
}
__device__ __forceinline__ void mma_bf16(float* c, const uint32_t* a, const uint32_t* b) {
    asm volatile("mma.sync.aligned.m16n8k16.row.col.f32.bf16.bf16.f32 "
                 "{%0,%1,%2,%3}, {%4,%5,%6,%7}, {%8,%9}, {%0,%1,%2,%3};"
                 : "+f"(c[0]), "+f"(c[1]), "+f"(c[2]), "+f"(c[3])
                 : "r"(a[0]), "r"(a[1]), "r"(a[2]), "r"(a[3]), "r"(b[0]), "r"(b[1]));
}
__device__ __forceinline__ void mma_tf32(float* c, const uint32_t* a, const uint32_t* b) {
    asm volatile("mma.sync.aligned.m16n8k8.row.col.f32.tf32.tf32.f32 "
                 "{%0,%1,%2,%3}, {%4,%5,%6,%7}, {%8,%9}, {%0,%1,%2,%3};"
                 : "+f"(c[0]), "+f"(c[1]), "+f"(c[2]), "+f"(c[3])
                 : "r"(a[0]), "r"(a[1]), "r"(a[2]), "r"(a[3]), "r"(b[0]), "r"(b[1]));
}
__device__ __forceinline__ uint32_t pack2bf(float a, float b) {
    __nv_bfloat162 t = __floats2bfloat162_rn(a, b);
    return *(uint32_t*)&t;
}
__device__ __forceinline__ uint32_t f2tf(float x) {
    uint32_t r;
    asm("cvt.rna.tf32.f32 %0, %1;" : "=r"(r) : "f"(x));
    return r;
}

// ============================================================
// Fold BN into conv1x1
// ============================================================
__global__ void fold_kernel(const float* __restrict__ Wq, const float* __restrict__ bq,
                            const float* __restrict__ gq, const float* __restrict__ betaq,
                            const float* __restrict__ mq, const float* __restrict__ vq,
                            const float* __restrict__ Wk, const float* __restrict__ bk,
                            const float* __restrict__ gk, const float* __restrict__ betak,
                            const float* __restrict__ mk, const float* __restrict__ vk)
{
    int idx = blockIdx.x * blockDim.x + threadIdx.x;
    if (idx >= Cdim * Cdim) return;
    int o = idx >> 8;
    float sq = gq[o] * rsqrtf(vq[o] + BNEPS);
    float sk = gk[o] * rsqrtf(vk[o] + BNEPS);
    g_WfQ[idx] = Wq[idx] * sq;
    g_WfK[idx] = Wk[idx] * sk;
    if ((idx & 255) == 0) {
        g_bfQ[o] = (bq[o] - mq[o]) * sq + betaq[o];
        g_bfK[o] = (bk[o] - mk[o]) * sk + betak[o];
    }
}

// ============================================================
// Projection GEMM via bf16 mma: dst[o][n] = sum_c Wf[o][c] X[c][n] + bf[o]
// grid (18 n-tiles, 2 o-tiles, 32 = p*8+b), 256 threads (8 warps).
// Warp w: o rows [o0 + w*16, +16), all 128 n of the tile.
// smem: Ws bf16 [128][264] (528B rows) + Xs bf16 [32][136] (272B rows)
// ============================================================
#define PJ_WOFF 0
#define PJ_XOFF 67584
#define PJ_SMEM (67584 + 32*272)

__global__ void __launch_bounds__(256, 2)
proj_kernel(const float* __restrict__ fleft, const float* __restrict__ fright)
{
    extern __shared__ char sm[];
    uint32_t sb = smem_u32(sm);
    int tid = threadIdx.x;
    int t = tid & 31, w = tid >> 5;

    int z = blockIdx.z;
    int p = z >> 3, b = z & 7;
    const float* X  = ((p & 1) ? fright : fleft) + b * CHW;
    const float* Wf = (p < 2) ? g_WfQ : g_WfK;
    const float* bf = (p < 2) ? g_bfQ : g_bfK;
    float* dst = ((p == 0) ? g_QL : (p == 1) ? g_QR : (p == 2) ? g_KL : g_KR) + b * CHW;

    int n0 = blockIdx.x * 128, o0 = blockIdx.y * 128;

    // load W tile [128 o][256 c] fp32 -> bf16
    #pragma unroll
    for (int it = 0; it < 32; it++) {
        int idx = tid + it * 256;
        int r = idx >> 6, c4 = idx & 63;
        float4 v = *(const float4*)(Wf + (o0 + r) * 256 + c4 * 4);
        *(uint2*)(sm + PJ_WOFF + r * 528 + c4 * 8) = make_uint2(pack2bf(v.x, v.y), pack2bf(v.z, v.w));
    }

    float oacc[16][4];
    #pragma unroll
    for (int i = 0; i < 16; i++)
        #pragma unroll
        for (int j = 0; j < 4; j++) oacc[i][j] = 0.0f;

    uint32_t aW = sb + PJ_WOFF + (w * 16 + (t & 7) + ((t >> 3) & 1) * 8) * 528 + (t >> 4) * 16;
    uint32_t bX = sb + PJ_XOFF + (t & 15) * 272;

    #pragma unroll 1
    for (int ch = 0; ch < 8; ch++) {
        __syncthreads();
        // load X chunk [32 c][128 n] fp32 -> bf16
        #pragma unroll
        for (int it = 0; it < 4; it++) {
            int idx = tid + it * 256;
            int rc = idx >> 5, n4 = idx & 31;
            float4 v = *(const float4*)(X + (ch * 32 + rc) * HW + n0 + n4 * 4);
            *(uint2*)(sm + PJ_XOFF + rc * 272 + n4 * 8) = make_uint2(pack2bf(v.x, v.y), pack2bf(v.z, v.w));
        }
        __syncthreads();

        #pragma unroll
        for (int ksl = 0; ksl < 2; ksl++) {
            uint32_t a[4];
            ldsm_x4(aW + ch * 64 + ksl * 32, a[0], a[1], a[2], a[3]);
            #pragma unroll
            for (int nt = 0; nt < 16; nt++) {
                uint32_t bb[2];
                ldsm_x2t(bX + ksl * 16 * 272 + nt * 16, bb[0], bb[1]);
                mma_bf16(oacc[nt], a, bb);
            }
        }
    }

    // epilogue: + bias, store fp32
    int r0 = o0 + w * 16 + (t >> 2);
    float b0 = bf[r0], b1 = bf[r0 + 8];
    #pragma unroll
    for (int nt = 0; nt < 16; nt++) {
        int col = n0 + nt * 8 + (t & 3) * 2;
        *(float2*)(dst + r0 * HW + col) = make_float2(oacc[nt][0] + b0, oacc[nt][1] + b0);
        *(float2*)(dst + (r0 + 8) * HW + col) = make_float2(oacc[nt][2] + b1, oacc[nt][3] + b1);
    }
}

// ============================================================
// Tensor flash attention (mma.sync): 128 q-rows/CTA, 36 key tiles of 64.
// 512 threads = 16 warps: g = w>>1 (16-row group), h = w&1 (key/d half).
// S bf16 mma; softmax no-max (__expf); P,V tf32 mma; O in regs.
// smem: Qs bf16[128][264] | Ks bf16[64][264] | Vs f32[64][264] | Ps f32[128][68] | li[128]
// ============================================================
#define AQOFF 0
#define AKOFF 67584
#define AVOFF 101376
#define APOFF 168960
#define ALOFF 203776
#define ATT_SMEM 204288

__global__ void __launch_bounds__(512, 1)
attn_kernel(const float* __restrict__ fleft, const float* __restrict__ fright,
            float* __restrict__ out)
{
    extern __shared__ char sm[];
    uint32_t sb = smem_u32(sm);
    int tid = threadIdx.x;
    int t = tid & 31, w = tid >> 5;
    int g = w >> 1, h = w & 1;

    int u = blockIdx.y;
    int att = u >> 3, b = u & 7;
    const float* Q = (att == 0 ? g_QL : g_QR) + b * CHW;
    const float* K = (att == 0 ? g_KR : g_KL) + b * CHW;
    const float* V = (att == 0 ? fright : fleft) + b * CHW;
    float* O = out + att * (Bsz * CHW) + b * CHW;
    int q0 = blockIdx.x * 128;

    if (tid < 128) *(float*)(sm + ALOFF + tid * 4) = 0.0f;

    // load Q tile [128][256] fp32 -> bf16
    #pragma unroll
    for (int it = 0; it < 16; it++) {
        int idx = tid + it * 512;
        int r = idx >> 6, d4 = idx & 63;
        float4 v = *(const float4*)(Q + (q0 + r) * 256 + d4 * 4);
        *(uint2*)(sm + AQOFF + r * 528 + d4 * 8) = make_uint2(pack2bf(v.x, v.y), pack2bf(v.z, v.w));
    }

    int m0 = g * 16;            // row group base
    int n0 = h * 32;            // key half base (S phase)
    int nd0 = h * 128;          // d half base (PV phase)

    uint32_t aQ = sb + AQOFF + (m0 + (t & 7) + ((t >> 3) & 1) * 8) * 528 + (t >> 4) * 16;
    uint32_t bK = sb + AKOFF + (n0 + (t & 7)) * 528 + ((t >> 3) & 1) * 16;
    int r0 = m0 + (t >> 2);
    uint32_t aP = sb + APOFF + r0 * 272 + (t & 3) * 4;
    uint32_t bV = sb + AVOFF + (t & 3) * 1056 + (nd0 + (t >> 2)) * 4;

    float oacc[16][4];
    #pragma unroll
    for (int i = 0; i < 16; i++)
        #pragma unroll
        for (int j = 0; j < 4; j++) oacc[i][j] = 0.0f;
    float li0 = 0.0f, li1 = 0.0f;

    #pragma unroll 1
    for (int kt = 0; kt < 36; kt++) {
        int k0 = kt * 64;
        __syncthreads();   // prev PV done -> K/V/P buffers free
        // load K tile [64][256] -> bf16, V tile [64][256] -> tf32
        #pragma unroll
        for (int it = 0; it < 8; it++) {
            int idx = tid + it * 512;
            int r = idx >> 6, d4 = idx & 63;
            float4 kv = *(const float4*)(K + (k0 + r) * 256 + d4 * 4);
            *(uint2*)(sm + AKOFF + r * 528 + d4 * 8) = make_uint2(pack2bf(kv.x, kv.y), pack2bf(kv.z, kv.w));
            float4 vv = *(const float4*)(V + (k0 + r) * 256 + d4 * 4);
            uint4 tv = make_uint4(f2tf(vv.x), f2tf(vv.y), f2tf(vv.z), f2tf(vv.w));
            *(uint4*)(sm + AVOFF + r * 1056 + d4 * 16) = tv;
        }
        __syncthreads();

        // ---- S = Q K^T (bf16), warp computes S[16 x 32] ----
        float sacc[4][4];
        #pragma unroll
        for (int i = 0; i < 4; i++)
            #pragma unroll
            for (int j = 0; j < 4; j++) sacc[i][j] = 0.0f;
        #pragma unroll
        for (int ks = 0; ks < 16; ks++) {
            uint32_t a[4];
            ldsm_x4(aQ + ks * 32, a[0], a[1], a[2], a[3]);
            #pragma unroll
            for (int nt = 0; nt < 4; nt++) {
                uint32_t bb[2];
                ldsm_x2(bK + nt * 8 * 528 + ks * 32, bb[0], bb[1]);
                mma_bf16(sacc[nt], a, bb);
            }
        }

        // ---- softmax (no max subtraction) + store P (tf32) ----
        #pragma unroll
        for (int nt = 0; nt < 4; nt++) {
            float p0 = __expf(sacc[nt][0] * INV_C);
            float p1 = __expf(sacc[nt][1] * INV_C);
            float p2 = __expf(sacc[nt][2] * INV_C);
            float p3 = __expf(sacc[nt][3] * INV_C);
            li0 += p0 + p1; li1 += p2 + p3;
            int col = n0 + nt * 8 + (t & 3) * 2;
            *(uint2*)(sm + APOFF + r0 * 272 + col * 4) = make_uint2(f2tf(p0), f2tf(p1));
            *(uint2*)(sm + APOFF + (r0 + 8) * 272 + col * 4) = make_uint2(f2tf(p2), f2tf(p3));
        }
        __syncthreads();   // P complete

        // ---- O += P @ V (tf32), warp computes O[16 x 128] ----
        #pragma unroll
        for (int ks = 0; ks < 8; ks++) {
            uint32_t a[4];
            a[0] = *(uint32_t*)(sm + (aP - sb) + ks * 32);
            a[1] = *(uint32_t*)(sm + (aP - sb) + 8 * 272 + ks * 32);
            a[2] = *(uint32_t*)(sm + (aP - sb) + 16 + ks * 32);
            a[3] = *(uint32_t*)(sm + (aP - sb) + 8 * 272 + 16 + ks * 32);
            uint32_t vbase = (bV - sb) + ks * 8 * 1056;
            #pragma unroll
            for (int nt = 0; nt < 16; nt++) {
                uint32_t bb[2];
                bb[0] = *(uint32_t*)(sm + vbase + nt * 32);
                bb[1] = *(uint32_t*)(sm + vbase + 4 * 1056 + nt * 32);
                mma_tf32(oacc[nt], a, bb);
            }
        }
    }

    // ---- li reduction ----
    li0 += __shfl_xor_sync(0xFFFFFFFFu, li0, 1);
    li0 += __shfl_xor_sync(0xFFFFFFFFu, li0, 2);
    li1 += __shfl_xor_sync(0xFFFFFFFFu, li1, 1);
    li1 += __shfl_xor_sync(0xFFFFFFFFu, li1, 2);
    if ((t & 3) == 0) {
        atomicAdd((float*)(sm + ALOFF + r0 * 4), li0);
        atomicAdd((float*)(sm + ALOFF + (r0 + 8) * 4), li1);
    }
    __syncthreads();

    // ---- epilogue: O[r][d]/li -> out[d*HW + q0 + r] ----
    float rl0 = 1.0f / *(float*)(sm + ALOFF + r0 * 4);
    float rl1 = 1.0f / *(float*)(sm + ALOFF + (r0 + 8) * 4);
    #pragma unroll
    for (int nt = 0; nt < 16; nt++) {
        int col = nd0 + nt * 8 + (t & 3) * 2;
        O[col * HW + q0 + r0]           = oacc[nt][0] * rl0;
        O[(col + 1) * HW + q0 + r0]     = oacc[nt][1] * rl0;
        O[col * HW + q0 + r0 + 8]       = oacc[nt][2] * rl1;
        O[(col + 1) * HW + q0 + r0 + 8] = oacc[nt][3] * rl1;
    }
}

extern "C" void kernel_launch(void* const* d_in, const int* in_sizes, int n_in,
                              void* d_out, int out_size)
{
    const float* fea_left  = (const float*)d_in[0];
    const float* fea_right = (const float*)d_in[1];
    const float* Wq    = (const float*)d_in[2];
    const float* bq    = (const float*)d_in[3];
    const float* gq    = (const float*)d_in[4];
    const float* betaq = (const float*)d_in[5];
    const float* mq    = (const float*)d_in[6];
    const float* vq    = (const float*)d_in[7];
    const float* Wk    = (const float*)d_in[8];
    const float* bk    = (const float*)d_in[9];
    const float* gk    = (const float*)d_in[10];
    const float* betak = (const float*)d_in[11];
    const float* mk    = (const float*)d_in[12];
    const float* vk    = (const float*)d_in[13];
    float* out = (float*)d_out;

    fold_kernel<<<256, 256>>>(Wq, bq, gq, betaq, mq, vq, Wk, bk, gk, betak, mk, vk);

    cudaFuncSetAttribute(proj_kernel, cudaFuncAttributeMaxDynamicSharedMemorySize, PJ_SMEM);
    proj_kernel<<<dim3(18, 2, 32), 256, PJ_SMEM>>>(fea_left, fea_right);

    cudaFuncSetAttribute(attn_kernel, cudaFuncAttributeMaxDynamicSharedMemorySize, ATT_SMEM);
    attn_kernel<<<dim3(18, 16), 512, ATT_SMEM>>>(fea_left, fea_right, out);
}

// round 9
// speedup vs baseline: 5.6691x; 1.1231x over previous
#include <cuda_runtime.h>
#include <cuda_bf16.h>
#include <cstdint>
#include <math.h>

#define Bsz 8
#define Cdim 256
#define HW 2304
#define CHW (Cdim*HW)          // 589824
#define BNEPS 1e-5f
#define INV_C (1.0f/256.0f)

// ---- static scratch (allocation-free) ----
__device__ __nv_bfloat16 g_QbL[Bsz*CHW];
__device__ __nv_bfloat16 g_QbR[Bsz*CHW];
__device__ __nv_bfloat16 g_KbL[Bsz*CHW];
__device__ __nv_bfloat16 g_KbR[Bsz*CHW];
__device__ float g_VfL[Bsz*CHW];     // V pre-rounded to tf32 (fp32 bits)
__device__ float g_VfR[Bsz*CHW];
__device__ float g_WfQ[Cdim*Cdim];
__device__ float g_WfK[Cdim*Cdim];
__device__ float g_bfQ[Cdim];
__device__ float g_bfK[Cdim];

// ============================================================
// helpers
// ============================================================
__device__ __forceinline__ uint32_t smem_u32(const void* p) {
    uint32_t a;
    asm("{ .reg .u64 t; cvta.to.shared.u64 t, %1; cvt.u32.u64 %0, t; }" : "=r"(a) : "l"(p));
    return a;
}
__device__ __forceinline__ void ldsm_x4(uint32_t a, uint32_t& r0, uint32_t& r1, uint32_t& r2, uint32_t& r3) {
    asm volatile("ldmatrix.sync.aligned.m8n8.x4.shared.b16 {%0,%1,%2,%3}, [%4];"
                 : "=r"(r0), "=r"(r1), "=r"(r2), "=r"(r3) : "r"(a));
}
__device__ __forceinline__ void ldsm_x2(uint32_t a, uint32_t& r0, uint32_t& r1) {
    asm volatile("ldmatrix.sync.aligned.m8n8.x2.shared.b16 {%0,%1}, [%2];"
                 : "=r"(r0), "=r"(r1) : "r"(a));
}
__device__ __forceinline__ void ldsm_x2t(uint32_t a, uint32_t& r0, uint32_t& r1) {
    asm volatile("ldmatrix.sync.aligned.m8n8.x2.trans.shared.b16 {%0,%1}, [%2];"
                 : "=r"(r0), "=r"(r1) : "r"(a));
}
__device__ __forceinline__ void mma_bf16(float* c, const uint32_t* a, const uint32_t* b) {
    asm volatile("mma.sync.aligned.m16n8k16.row.col.f32.bf16.bf16.f32 "
                 "{%0,%1,%2,%3}, {%4,%5,%6,%7}, {%8,%9}, {%0,%1,%2,%3};"
                 : "+f"(c[0]), "+f"(c[1]), "+f"(c[2]), "+f"(c[3])
                 : "r"(a[0]), "r"(a[1]), "r"(a[2]), "r"(a[3]), "r"(b[0]), "r"(b[1]));
}
__device__ __forceinline__ void mma_tf32(float* c, const uint32_t* a, const uint32_t* b) {
    asm volatile("mma.sync.aligned.m16n8k8.row.col.f32.tf32.tf32.f32 "
                 "{%0,%1,%2,%3}, {%4,%5,%6,%7}, {%8,%9}, {%0,%1,%2,%3};"
                 : "+f"(c[0]), "+f"(c[1]), "+f"(c[2]), "+f"(c[3])
                 : "r"(a[0]), "r"(a[1]), "r"(a[2]), "r"(a[3]), "r"(b[0]), "r"(b[1]));
}
__device__ __forceinline__ uint32_t pack2bf(float a, float b) {
    __nv_bfloat162 t = __floats2bfloat162_rn(a, b);
    return *(uint32_t*)&t;
}
__device__ __forceinline__ uint32_t f2tf(float x) {
    uint32_t r;
    asm("cvt.rna.tf32.f32 %0, %1;" : "=r"(r) : "f"(x));
    return r;
}
#define CP_ASYNC16(dst, src) \
    asm volatile("cp.async.cg.shared.global [%0], [%1], 16;" :: "r"(dst), "l"(src) : "memory")
#define CP_COMMIT() asm volatile("cp.async.commit_group;" ::: "memory")
#define CP_WAIT0()  asm volatile("cp.async.wait_group 0;" ::: "memory")

// ============================================================
// Fold BN into conv1x1
// ============================================================
__global__ void fold_kernel(const float* __restrict__ Wq, const float* __restrict__ bq,
                            const float* __restrict__ gq, const float* __restrict__ betaq,
                            const float* __restrict__ mq, const float* __restrict__ vq,
                            const float* __restrict__ Wk, const float* __restrict__ bk,
                            const float* __restrict__ gk, const float* __restrict__ betak,
                            const float* __restrict__ mk, const float* __restrict__ vk)
{
    int idx = blockIdx.x * blockDim.x + threadIdx.x;
    if (idx >= Cdim * Cdim) return;
    int o = idx >> 8;
    float sq = gq[o] * rsqrtf(vq[o] + BNEPS);
    float sk = gk[o] * rsqrtf(vk[o] + BNEPS);
    g_WfQ[idx] = Wq[idx] * sq;
    g_WfK[idx] = Wk[idx] * sk;
    if ((idx & 255) == 0) {
        g_bfQ[o] = (bq[o] - mq[o]) * sq + betaq[o];
        g_bfK[o] = (bk[o] - mk[o]) * sk + betak[o];
    }
}

// ============================================================
// V convert: fea fp32 -> tf32-rounded fp32 scratch (both sides)
// ============================================================
__global__ void vconv_kernel(const float* __restrict__ fleft, const float* __restrict__ fright)
{
    int i = blockIdx.x * blockDim.x + threadIdx.x;      // float4 index
    const int n4 = (Bsz * CHW) / 4;
    if (i >= n4) return;
    float4 a = ((const float4*)fleft)[i];
    float4 b = ((const float4*)fright)[i];
    ((uint4*)g_VfL)[i] = make_uint4(f2tf(a.x), f2tf(a.y), f2tf(a.z), f2tf(a.w));
    ((uint4*)g_VfR)[i] = make_uint4(f2tf(b.x), f2tf(b.y), f2tf(b.z), f2tf(b.w));
}

// ============================================================
// Projection GEMM via bf16 mma: dst[o][n] = sum_c Wf[o][c] X[c][n] + bf[o]
// grid (18 n-tiles, 2 o-tiles, 32 = p*8+b), 256 threads (8 warps). bf16 output.
// ============================================================
#define PJ_WOFF 0
#define PJ_XOFF 67584
#define PJ_SMEM (67584 + 32*272)

__global__ void __launch_bounds__(256, 2)
proj_kernel(const float* __restrict__ fleft, const float* __restrict__ fright)
{
    extern __shared__ char sm[];
    uint32_t sb = smem_u32(sm);
    int tid = threadIdx.x;
    int t = tid & 31, w = tid >> 5;

    int z = blockIdx.z;
    int p = z >> 3, b = z & 7;
    const float* X  = ((p & 1) ? fright : fleft) + b * CHW;
    const float* Wf = (p < 2) ? g_WfQ : g_WfK;
    const float* bf = (p < 2) ? g_bfQ : g_bfK;
    __nv_bfloat16* dst =
        ((p == 0) ? g_QbL : (p == 1) ? g_QbR : (p == 2) ? g_KbL : g_KbR) + b * CHW;

    int n0 = blockIdx.x * 128, o0 = blockIdx.y * 128;

    // load W tile [128 o][256 c] fp32 -> bf16
    #pragma unroll
    for (int it = 0; it < 32; it++) {
        int idx = tid + it * 256;
        int r = idx >> 6, c4 = idx & 63;
        float4 v = *(const float4*)(Wf + (o0 + r) * 256 + c4 * 4);
        *(uint2*)(sm + PJ_WOFF + r * 528 + c4 * 8) = make_uint2(pack2bf(v.x, v.y), pack2bf(v.z, v.w));
    }

    float oacc[16][4];
    #pragma unroll
    for (int i = 0; i < 16; i++)
        #pragma unroll
        for (int j = 0; j < 4; j++) oacc[i][j] = 0.0f;

    uint32_t aW = sb + PJ_WOFF + (w * 16 + (t & 7) + ((t >> 3) & 1) * 8) * 528 + (t >> 4) * 16;
    uint32_t bX = sb + PJ_XOFF + (t & 15) * 272;

    #pragma unroll 1
    for (int ch = 0; ch < 8; ch++) {
        __syncthreads();
        #pragma unroll
        for (int it = 0; it < 4; it++) {
            int idx = tid + it * 256;
            int rc = idx >> 5, n4 = idx & 31;
            float4 v = *(const float4*)(X + (ch * 32 + rc) * HW + n0 + n4 * 4);
            *(uint2*)(sm + PJ_XOFF + rc * 272 + n4 * 8) = make_uint2(pack2bf(v.x, v.y), pack2bf(v.z, v.w));
        }
        __syncthreads();

        #pragma unroll
        for (int ksl = 0; ksl < 2; ksl++) {
            uint32_t a[4];
            ldsm_x4(aW + ch * 64 + ksl * 32, a[0], a[1], a[2], a[3]);
            #pragma unroll
            for (int nt = 0; nt < 16; nt++) {
                uint32_t bb[2];
                ldsm_x2t(bX + ksl * 16 * 272 + nt * 16, bb[0], bb[1]);
                mma_bf16(oacc[nt], a, bb);
            }
        }
    }

    // epilogue: + bias, store bf16
    int r0 = o0 + w * 16 + (t >> 2);
    float b0 = bf[r0], b1 = bf[r0 + 8];
    #pragma unroll
    for (int nt = 0; nt < 16; nt++) {
        int col = n0 + nt * 8 + (t & 3) * 2;
        *(uint32_t*)(dst + r0 * HW + col)       = pack2bf(oacc[nt][0] + b0, oacc[nt][1] + b0);
        *(uint32_t*)(dst + (r0 + 8) * HW + col) = pack2bf(oacc[nt][2] + b1, oacc[nt][3] + b1);
    }
}

// ============================================================
// Flash attention: bf16 S, tf32 PV (R6 numerics), cp.async double-buffered.
// 128 q-rows/CTA, 72 key tiles of 32. 512 threads = 16 warps:
// g = w>>1 (16-row group), h = w&1 (16-key half for S, 128-d half for PV).
// smem: Qs bf16[128][528B] | Ks bf16[2][32][528B] | Vs f32[2][32][1056B]
//       | Ps f32[128][272B] | li[128]
// ============================================================
#define AQOFF 0
#define AKOFF 67584
#define AVOFF 101376
#define APOFF 168960
#define ALOFF 203776
#define ATT_SMEM 204288
#define KTILE 16896          // 32*528
#define VTILE 33792          // 32*1056

__global__ void __launch_bounds__(512, 1)
attn_kernel(float* __restrict__ out)
{
    extern __shared__ char sm[];
    uint32_t sb = smem_u32(sm);
    int tid = threadIdx.x;
    int t = tid & 31, w = tid >> 5;
    int g = w >> 1, h = w & 1;

    int u = blockIdx.y;
    int att = u >> 3, b = u & 7;
    const __nv_bfloat16* Q = (att == 0 ? g_QbL : g_QbR) + b * CHW;
    const __nv_bfloat16* K = (att == 0 ? g_KbR : g_KbL) + b * CHW;
    const float*         V = (att == 0 ? g_VfR : g_VfL) + b * CHW;
    float* O = out + att * (Bsz * CHW) + b * CHW;
    int q0 = blockIdx.x * 128;

    if (tid < 128) *(float*)(sm + ALOFF + tid * 4) = 0.0f;

    // Q tile via cp.async: 128 rows x 32 chunks of 16B
    #pragma unroll
    for (int it = 0; it < 8; it++) {
        int idx = tid + it * 512;
        int r = idx >> 5, c16 = idx & 31;
        CP_ASYNC16(sb + AQOFF + r * 528 + c16 * 16, (const char*)(Q + (q0 + r) * 256) + c16 * 16);
    }
    // K/V tile 0 into buffer 0
    #pragma unroll
    for (int it = 0; it < 2; it++) {     // K: 32 rows x 32 chunks = 1024
        int idx = tid + it * 512;
        int r = idx >> 5, c16 = idx & 31;
        CP_ASYNC16(sb + AKOFF + r * 528 + c16 * 16, (const char*)(K + r * 256) + c16 * 16);
    }
    #pragma unroll
    for (int it = 0; it < 4; it++) {     // V: 32 rows x 64 chunks = 2048
        int idx = tid + it * 512;
        int r = idx >> 6, c16 = idx & 63;
        CP_ASYNC16(sb + AVOFF + r * 1056 + c16 * 16, (const char*)(V + r * 256) + c16 * 16);
    }
    CP_COMMIT();

    int m0 = g * 16;
    int n0 = h * 16;            // key half (S phase): 16 of 32 keys
    int nd0 = h * 128;          // d half (PV phase)

    uint32_t aQ = sb + AQOFF + (m0 + (t & 7) + ((t >> 3) & 1) * 8) * 528 + (t >> 4) * 16;
    int r0 = m0 + (t >> 2);
    uint32_t aPb = sb + APOFF + r0 * 272 + (t & 3) * 4;

    float oacc[16][4];
    #pragma unroll
    for (int i = 0; i < 16; i++)
        #pragma unroll
        for (int j = 0; j < 4; j++) oacc[i][j] = 0.0f;
    float li0 = 0.0f, li1 = 0.0f;

    #pragma unroll 1
    for (int kt = 0; kt < 72; kt++) {
        int buf = kt & 1;
        uint32_t kbase = sb + AKOFF + buf * KTILE;
        uint32_t vbase = sb + AVOFF + buf * VTILE;

        CP_WAIT0();
        __syncthreads();      // tile kt resident; prev iter's P/V consumers done

        // prefetch tile kt+1 into other buffer (overlaps with compute below)
        if (kt < 71) {
            int k0n = (kt + 1) * 32;
            uint32_t kd = sb + AKOFF + (buf ^ 1) * KTILE;
            uint32_t vd = sb + AVOFF + (buf ^ 1) * VTILE;
            #pragma unroll
            for (int it = 0; it < 2; it++) {
                int idx = tid + it * 512;
                int r = idx >> 5, c16 = idx & 31;
                CP_ASYNC16(kd + r * 528 + c16 * 16, (const char*)(K + (k0n + r) * 256) + c16 * 16);
            }
            #pragma unroll
            for (int it = 0; it < 4; it++) {
                int idx = tid + it * 512;
                int r = idx >> 6, c16 = idx & 63;
                CP_ASYNC16(vd + r * 1056 + c16 * 16, (const char*)(V + (k0n + r) * 256) + c16 * 16);
            }
            CP_COMMIT();
        }

        // ---- S = Q K^T (bf16), warp computes S[16 x 16] ----
        uint32_t bK = kbase + (n0 + (t & 7)) * 528 + ((t >> 3) & 1) * 16;
        float sacc[2][4];
        #pragma unroll
        for (int i = 0; i < 2; i++)
            #pragma unroll
            for (int j = 0; j < 4; j++) sacc[i][j] = 0.0f;
        #pragma unroll
        for (int ks = 0; ks < 16; ks++) {
            uint32_t a[4];
            ldsm_x4(aQ + ks * 32, a[0], a[1], a[2], a[3]);
            #pragma unroll
            for (int nt = 0; nt < 2; nt++) {
                uint32_t bb[2];
                ldsm_x2(bK + nt * 8 * 528 + ks * 32, bb[0], bb[1]);
                mma_bf16(sacc[nt], a, bb);
            }
        }

        // ---- softmax (no max subtraction) + store P (tf32-rounded fp32) ----
        #pragma unroll
        for (int nt = 0; nt < 2; nt++) {
            float p0 = __expf(sacc[nt][0] * INV_C);
            float p1 = __expf(sacc[nt][1] * INV_C);
            float p2 = __expf(sacc[nt][2] * INV_C);
            float p3 = __expf(sacc[nt][3] * INV_C);
            li0 += p0 + p1; li1 += p2 + p3;
            int col = n0 + nt * 8 + (t & 3) * 2;
            *(uint2*)(sm + APOFF + r0 * 272 + col * 4)       = make_uint2(f2tf(p0), f2tf(p1));
            *(uint2*)(sm + APOFF + (r0 + 8) * 272 + col * 4) = make_uint2(f2tf(p2), f2tf(p3));
        }
        __syncthreads();   // P complete

        // ---- O += P @ V (tf32), warp computes O[16 x 128] ----
        uint32_t bV = vbase + (t & 3) * 1056 + (nd0 + (t >> 2)) * 4;
        #pragma unroll
        for (int ks = 0; ks < 4; ks++) {
            uint32_t a[4];
            a[0] = *(uint32_t*)(sm + (aPb - sb) + ks * 32);
            a[1] = *(uint32_t*)(sm + (aPb - sb) + 8 * 272 + ks * 32);
            a[2] = *(uint32_t*)(sm + (aPb - sb) + 16 + ks * 32);
            a[3] = *(uint32_t*)(sm + (aPb - sb) + 8 * 272 + 16 + ks * 32);
            uint32_t vb = (bV - sb) + ks * 8 * 1056;
            #pragma unroll
            for (int nt = 0; nt < 16; nt++) {
                uint32_t bb[2];
                bb[0] = *(uint32_t*)(sm + vb + nt * 32);
                bb[1] = *(uint32_t*)(sm + vb + 4 * 1056 + nt * 32);
                mma_tf32(oacc[nt], a, bb);
            }
        }
    }

    // ---- li reduction ----
    li0 += __shfl_xor_sync(0xFFFFFFFFu, li0, 1);
    li0 += __shfl_xor_sync(0xFFFFFFFFu, li0, 2);
    li1 += __shfl_xor_sync(0xFFFFFFFFu, li1, 1);
    li1 += __shfl_xor_sync(0xFFFFFFFFu, li1, 2);
    if ((t & 3) == 0) {
        atomicAdd((float*)(sm + ALOFF + r0 * 4), li0);
        atomicAdd((float*)(sm + ALOFF + (r0 + 8) * 4), li1);
    }
    __syncthreads();

    // ---- epilogue: O[r][d]/li -> out[d*HW + q0 + r] ----
    float rl0 = 1.0f / *(float*)(sm + ALOFF + r0 * 4);
    float rl1 = 1.0f / *(float*)(sm + ALOFF + (r0 + 8) * 4);
    #pragma unroll
    for (int nt = 0; nt < 16; nt++) {
        int col = nd0 + nt * 8 + (t & 3) * 2;
        O[col * HW + q0 + r0]           = oacc[nt][0] * rl0;
        O[(col + 1) * HW + q0 + r0]     = oacc[nt][1] * rl0;
        O[col * HW + q0 + r0 + 8]       = oacc[nt][2] * rl1;
        O[(col + 1) * HW + q0 + r0 + 8] = oacc[nt][3] * rl1;
    }
}

extern "C" void kernel_launch(void* const* d_in, const int* in_sizes, int n_in,
                              void* d_out, int out_size)
{
    const float* fea_left  = (const float*)d_in[0];
    const float* fea_right = (const float*)d_in[1];
    const float* Wq    = (const float*)d_in[2];
    const float* bq    = (const float*)d_in[3];
    const float* gq    = (const float*)d_in[4];
    const float* betaq = (const float*)d_in[5];
    const float* mq    = (const float*)d_in[6];
    const float* vq    = (const float*)d_in[7];
    const float* Wk    = (const float*)d_in[8];
    const float* bk    = (const float*)d_in[9];
    const float* gk    = (const float*)d_in[10];
    const float* betak = (const float*)d_in[11];
    const float* mk    = (const float*)d_in[12];
    const float* vk    = (const float*)d_in[13];
    float* out = (float*)d_out;

    fold_kernel<<<256, 256>>>(Wq, bq, gq, betaq, mq, vq, Wk, bk, gk, betak, mk, vk);
    vconv_kernel<<<(Bsz * CHW / 4 + 255) / 256, 256>>>(fea_left, fea_right);

    cudaFuncSetAttribute(proj_kernel, cudaFuncAttributeMaxDynamicSharedMemorySize, PJ_SMEM);
    proj_kernel<<<dim3(18, 2, 32), 256, PJ_SMEM>>>(fea_left, fea_right);

    cudaFuncSetAttribute(attn_kernel, cudaFuncAttributeMaxDynamicSharedMemorySize, ATT_SMEM);
    attn_kernel<<<dim3(18, 16), 512, ATT_SMEM>>>(out);
}

// round 10
// speedup vs baseline: 6.4502x; 1.1378x over previous
#include <cuda_runtime.h>
#include <cuda_bf16.h>
#include <cstdint>
#include <math.h>

#define Bsz 8
#define Cdim 256
#define HW 2304
#define CHW (Cdim*HW)          // 589824
#define BNEPS 1e-5f
#define INV_C (1.0f/256.0f)

// ---- static scratch (allocation-free) ----
__device__ __nv_bfloat16 g_QbL[Bsz*CHW];
__device__ __nv_bfloat16 g_QbR[Bsz*CHW];
__device__ __nv_bfloat16 g_KbL[Bsz*CHW];
__device__ __nv_bfloat16 g_KbR[Bsz*CHW];
__device__ float g_VfL[Bsz*CHW];     // V pre-rounded to tf32 (fp32 bits)
__device__ float g_VfR[Bsz*CHW];
__device__ float g_WfQ[Cdim*Cdim];
__device__ float g_WfK[Cdim*Cdim];
__device__ float g_bfQ[Cdim];
__device__ float g_bfK[Cdim];

// ============================================================
// helpers
// ============================================================
__device__ __forceinline__ uint32_t smem_u32(const void* p) {
    uint32_t a;
    asm("{ .reg .u64 t; cvta.to.shared.u64 t, %1; cvt.u32.u64 %0, t; }" : "=r"(a) : "l"(p));
    return a;
}
__device__ __forceinline__ void ldsm_x4(uint32_t a, uint32_t& r0, uint32_t& r1, uint32_t& r2, uint32_t& r3) {
    asm volatile("ldmatrix.sync.aligned.m8n8.x4.shared.b16 {%0,%1,%2,%3}, [%4];"
                 : "=r"(r0), "=r"(r1), "=r"(r2), "=r"(r3) : "r"(a));
}
__device__ __forceinline__ void ldsm_x2(uint32_t a, uint32_t& r0, uint32_t& r1) {
    asm volatile("ldmatrix.sync.aligned.m8n8.x2.shared.b16 {%0,%1}, [%2];"
                 : "=r"(r0), "=r"(r1) : "r"(a));
}
__device__ __forceinline__ void ldsm_x2t(uint32_t a, uint32_t& r0, uint32_t& r1) {
    asm volatile("ldmatrix.sync.aligned.m8n8.x2.trans.shared.b16 {%0,%1}, [%2];"
                 : "=r"(r0), "=r"(r1) : "r"(a));
}
__device__ __forceinline__ void mma_bf16(float* c, const uint32_t* a, const uint32_t* b) {
    asm volatile("mma.sync.aligned.m16n8k16.row.col.f32.bf16.bf16.f32 "
                 "{%0,%1,%2,%3}, {%4,%5,%6,%7}, {%8,%9}, {%0,%1,%2,%3};"
                 : "+f"(c[0]), "+f"(c[1]), "+f"(c[2]), "+f"(c[3])
                 : "r"(a[0]), "r"(a[1]), "r"(a[2]), "r"(a[3]), "r"(b[0]), "r"(b[1]));
}
__device__ __forceinline__ void mma_tf32(float* c, const uint32_t* a, const uint32_t* b) {
    asm volatile("mma.sync.aligned.m16n8k8.row.col.f32.tf32.tf32.f32 "
                 "{%0,%1,%2,%3}, {%4,%5,%6,%7}, {%8,%9}, {%0,%1,%2,%3};"
                 : "+f"(c[0]), "+f"(c[1]), "+f"(c[2]), "+f"(c[3])
                 : "r"(a[0]), "r"(a[1]), "r"(a[2]), "r"(a[3]), "r"(b[0]), "r"(b[1]));
}
__device__ __forceinline__ uint32_t pack2bf(float a, float b) {
    __nv_bfloat162 t = __floats2bfloat162_rn(a, b);
    return *(uint32_t*)&t;
}
__device__ __forceinline__ uint32_t f2tf(float x) {
    uint32_t r;
    asm("cvt.rna.tf32.f32 %0, %1;" : "=r"(r) : "f"(x));
    return r;
}
#define CP_ASYNC16(dst, src) \
    asm volatile("cp.async.cg.shared.global [%0], [%1], 16;" :: "r"(dst), "l"(src) : "memory")
#define CP_COMMIT() asm volatile("cp.async.commit_group;" ::: "memory")
#define CP_WAIT0()  asm volatile("cp.async.wait_group 0;" ::: "memory")

// ============================================================
// Fold BN into conv1x1
// ============================================================
__global__ void fold_kernel(const float* __restrict__ Wq, const float* __restrict__ bq,
                            const float* __restrict__ gq, const float* __restrict__ betaq,
                            const float* __restrict__ mq, const float* __restrict__ vq,
                            const float* __restrict__ Wk, const float* __restrict__ bk,
                            const float* __restrict__ gk, const float* __restrict__ betak,
                            const float* __restrict__ mk, const float* __restrict__ vk)
{
    int idx = blockIdx.x * blockDim.x + threadIdx.x;
    if (idx >= Cdim * Cdim) return;
    int o = idx >> 8;
    float sq = gq[o] * rsqrtf(vq[o] + BNEPS);
    float sk = gk[o] * rsqrtf(vk[o] + BNEPS);
    g_WfQ[idx] = Wq[idx] * sq;
    g_WfK[idx] = Wk[idx] * sk;
    if ((idx & 255) == 0) {
        g_bfQ[o] = (bq[o] - mq[o]) * sq + betaq[o];
        g_bfK[o] = (bk[o] - mk[o]) * sk + betak[o];
    }
}

// ============================================================
// V convert: fea fp32 -> tf32-rounded fp32 scratch (both sides)
// ============================================================
__global__ void vconv_kernel(const float* __restrict__ fleft, const float* __restrict__ fright)
{
    int i = blockIdx.x * blockDim.x + threadIdx.x;      // float4 index
    const int n4 = (Bsz * CHW) / 4;
    if (i >= n4) return;
    float4 a = ((const float4*)fleft)[i];
    float4 b = ((const float4*)fright)[i];
    ((uint4*)g_VfL)[i] = make_uint4(f2tf(a.x), f2tf(a.y), f2tf(a.z), f2tf(a.w));
    ((uint4*)g_VfR)[i] = make_uint4(f2tf(b.x), f2tf(b.y), f2tf(b.z), f2tf(b.w));
}

// ============================================================
// Projection GEMM via bf16 mma (unchanged)
// ============================================================
#define PJ_WOFF 0
#define PJ_XOFF 67584
#define PJ_SMEM (67584 + 32*272)

__global__ void __launch_bounds__(256, 2)
proj_kernel(const float* __restrict__ fleft, const float* __restrict__ fright)
{
    extern __shared__ char sm[];
    uint32_t sb = smem_u32(sm);
    int tid = threadIdx.x;
    int t = tid & 31, w = tid >> 5;

    int z = blockIdx.z;
    int p = z >> 3, b = z & 7;
    const float* X  = ((p & 1) ? fright : fleft) + b * CHW;
    const float* Wf = (p < 2) ? g_WfQ : g_WfK;
    const float* bf = (p < 2) ? g_bfQ : g_bfK;
    __nv_bfloat16* dst =
        ((p == 0) ? g_QbL : (p == 1) ? g_QbR : (p == 2) ? g_KbL : g_KbR) + b * CHW;

    int n0 = blockIdx.x * 128, o0 = blockIdx.y * 128;

    #pragma unroll
    for (int it = 0; it < 32; it++) {
        int idx = tid + it * 256;
        int r = idx >> 6, c4 = idx & 63;
        float4 v = *(const float4*)(Wf + (o0 + r) * 256 + c4 * 4);
        *(uint2*)(sm + PJ_WOFF + r * 528 + c4 * 8) = make_uint2(pack2bf(v.x, v.y), pack2bf(v.z, v.w));
    }

    float oacc[16][4];
    #pragma unroll
    for (int i = 0; i < 16; i++)
        #pragma unroll
        for (int j = 0; j < 4; j++) oacc[i][j] = 0.0f;

    uint32_t aW = sb + PJ_WOFF + (w * 16 + (t & 7) + ((t >> 3) & 1) * 8) * 528 + (t >> 4) * 16;
    uint32_t bX = sb + PJ_XOFF + (t & 15) * 272;

    #pragma unroll 1
    for (int ch = 0; ch < 8; ch++) {
        __syncthreads();
        #pragma unroll
        for (int it = 0; it < 4; it++) {
            int idx = tid + it * 256;
            int rc = idx >> 5, n4 = idx & 31;
            float4 v = *(const float4*)(X + (ch * 32 + rc) * HW + n0 + n4 * 4);
            *(uint2*)(sm + PJ_XOFF + rc * 272 + n4 * 8) = make_uint2(pack2bf(v.x, v.y), pack2bf(v.z, v.w));
        }
        __syncthreads();

        #pragma unroll
        for (int ksl = 0; ksl < 2; ksl++) {
            uint32_t a[4];
            ldsm_x4(aW + ch * 64 + ksl * 32, a[0], a[1], a[2], a[3]);
            #pragma unroll
            for (int nt = 0; nt < 16; nt++) {
                uint32_t bb[2];
                ldsm_x2t(bX + ksl * 16 * 272 + nt * 16, bb[0], bb[1]);
                mma_bf16(oacc[nt], a, bb);
            }
        }
    }

    int r0 = o0 + w * 16 + (t >> 2);
    float b0 = bf[r0], b1 = bf[r0 + 8];
    #pragma unroll
    for (int nt = 0; nt < 16; nt++) {
        int col = n0 + nt * 8 + (t & 3) * 2;
        *(uint32_t*)(dst + r0 * HW + col)       = pack2bf(oacc[nt][0] + b0, oacc[nt][1] + b0);
        *(uint32_t*)(dst + (r0 + 8) * HW + col) = pack2bf(oacc[nt][2] + b1, oacc[nt][3] + b1);
    }
}

// ============================================================
// Flash attention: bf16 S, tf32 PV, cp.async double-buffered.
// 128 q-rows/CTA, 72 key tiles of 32. 256 threads = 8 warps:
// g = w>>1 owns 32 rows (two 16-row A-frags share every B-frag),
// h = w&1 (16-key half for S, 128-d half for PV).
// smem layout identical to R9 (204 KB).
// ============================================================
#define AQOFF 0
#define AKOFF 67584
#define AVOFF 101376
#define APOFF 168960
#define ALOFF 203776
#define ATT_SMEM 204288
#define KTILE 16896          // 32*528
#define VTILE 33792          // 32*1056

__global__ void __launch_bounds__(256, 1)
attn_kernel(float* __restrict__ out)
{
    extern __shared__ char sm[];
    uint32_t sb = smem_u32(sm);
    int tid = threadIdx.x;
    int t = tid & 31, w = tid >> 5;
    int g = w >> 1, h = w & 1;

    int u = blockIdx.y;
    int att = u >> 3, b = u & 7;
    const __nv_bfloat16* Q = (att == 0 ? g_QbL : g_QbR) + b * CHW;
    const __nv_bfloat16* K = (att == 0 ? g_KbR : g_KbL) + b * CHW;
    const float*         V = (att == 0 ? g_VfR : g_VfL) + b * CHW;
    float* O = out + att * (Bsz * CHW) + b * CHW;
    int q0 = blockIdx.x * 128;

    if (tid < 128) *(float*)(sm + ALOFF + tid * 4) = 0.0f;

    // Q tile via cp.async: 128 rows x 32 chunks of 16B
    #pragma unroll
    for (int it = 0; it < 16; it++) {
        int idx = tid + it * 256;
        int r = idx >> 5, c16 = idx & 31;
        CP_ASYNC16(sb + AQOFF + r * 528 + c16 * 16, (const char*)(Q + (q0 + r) * 256) + c16 * 16);
    }
    // K/V tile 0 into buffer 0
    #pragma unroll
    for (int it = 0; it < 4; it++) {     // K: 32 rows x 32 chunks
        int idx = tid + it * 256;
        int r = idx >> 5, c16 = idx & 31;
        CP_ASYNC16(sb + AKOFF + r * 528 + c16 * 16, (const char*)(K + r * 256) + c16 * 16);
    }
    #pragma unroll
    for (int it = 0; it < 8; it++) {     // V: 32 rows x 64 chunks
        int idx = tid + it * 256;
        int r = idx >> 6, c16 = idx & 63;
        CP_ASYNC16(sb + AVOFF + r * 1056 + c16 * 16, (const char*)(V + r * 256) + c16 * 16);
    }
    CP_COMMIT();

    int m0 = g * 32;            // 32-row group
    int n0 = h * 16;            // key half (S phase)
    int nd0 = h * 128;          // d half (PV phase)

    uint32_t aQ0 = sb + AQOFF + (m0 + (t & 7) + ((t >> 3) & 1) * 8) * 528 + (t >> 4) * 16;
    uint32_t aQ1 = aQ0 + 16 * 528;
    int r0 = m0 + (t >> 2);
    uint32_t aP0 = sb + APOFF + r0 * 272 + (t & 3) * 4;
    uint32_t aP1 = aP0 + 16 * 272;

    float oacc[2][16][4];
    #pragma unroll
    for (int f = 0; f < 2; f++)
        #pragma unroll
        for (int i = 0; i < 16; i++)
            #pragma unroll
            for (int j = 0; j < 4; j++) oacc[f][i][j] = 0.0f;
    float li00 = 0.0f, li01 = 0.0f, li10 = 0.0f, li11 = 0.0f;

    #pragma unroll 1
    for (int kt = 0; kt < 72; kt++) {
        int buf = kt & 1;
        uint32_t kbase = sb + AKOFF + buf * KTILE;
        uint32_t vbase = sb + AVOFF + buf * VTILE;

        CP_WAIT0();
        __syncthreads();      // tile kt resident; prev iter's P/V consumers done

        // prefetch tile kt+1 into other buffer
        if (kt < 71) {
            int k0n = (kt + 1) * 32;
            uint32_t kd = sb + AKOFF + (buf ^ 1) * KTILE;
            uint32_t vd = sb + AVOFF + (buf ^ 1) * VTILE;
            #pragma unroll
            for (int it = 0; it < 4; it++) {
                int idx = tid + it * 256;
                int r = idx >> 5, c16 = idx & 31;
                CP_ASYNC16(kd + r * 528 + c16 * 16, (const char*)(K + (k0n + r) * 256) + c16 * 16);
            }
            #pragma unroll
            for (int it = 0; it < 8; it++) {
                int idx = tid + it * 256;
                int r = idx >> 6, c16 = idx & 63;
                CP_ASYNC16(vd + r * 1056 + c16 * 16, (const char*)(V + (k0n + r) * 256) + c16 * 16);
            }
            CP_COMMIT();
        }

        // ---- S = Q K^T (bf16): warp computes S[32 x 16] via 2 A-frags ----
        uint32_t bK = kbase + (n0 + (t & 7)) * 528 + ((t >> 3) & 1) * 16;
        float sacc[2][2][4];
        #pragma unroll
        for (int f = 0; f < 2; f++)
            #pragma unroll
            for (int i = 0; i < 2; i++)
                #pragma unroll
                for (int j = 0; j < 4; j++) sacc[f][i][j] = 0.0f;
        #pragma unroll
        for (int ks = 0; ks < 16; ks++) {
            uint32_t a0[4], a1[4];
            ldsm_x4(aQ0 + ks * 32, a0[0], a0[1], a0[2], a0[3]);
            ldsm_x4(aQ1 + ks * 32, a1[0], a1[1], a1[2], a1[3]);
            #pragma unroll
            for (int nt = 0; nt < 2; nt++) {
                uint32_t bb[2];
                ldsm_x2(bK + nt * 8 * 528 + ks * 32, bb[0], bb[1]);
                mma_bf16(sacc[0][nt], a0, bb);
                mma_bf16(sacc[1][nt], a1, bb);
            }
        }

        // ---- softmax (no max subtraction) + store P (tf32-rounded fp32) ----
        #pragma unroll
        for (int f = 0; f < 2; f++) {
            int rf = r0 + f * 16;
            #pragma unroll
            for (int nt = 0; nt < 2; nt++) {
                float p0 = __expf(sacc[f][nt][0] * INV_C);
                float p1 = __expf(sacc[f][nt][1] * INV_C);
                float p2 = __expf(sacc[f][nt][2] * INV_C);
                float p3 = __expf(sacc[f][nt][3] * INV_C);
                if (f == 0) { li00 += p0 + p1; li01 += p2 + p3; }
                else        { li10 += p0 + p1; li11 += p2 + p3; }
                int col = n0 + nt * 8 + (t & 3) * 2;
                *(uint2*)(sm + APOFF + rf * 272 + col * 4)       = make_uint2(f2tf(p0), f2tf(p1));
                *(uint2*)(sm + APOFF + (rf + 8) * 272 + col * 4) = make_uint2(f2tf(p2), f2tf(p3));
            }
        }
        __syncthreads();   // P complete

        // ---- O += P @ V (tf32): each B-frag feeds both A-frags ----
        uint32_t bV = vbase + (t & 3) * 1056 + (nd0 + (t >> 2)) * 4;
        #pragma unroll
        for (int ks = 0; ks < 4; ks++) {
            uint32_t a0[4], a1[4];
            a0[0] = *(uint32_t*)(sm + (aP0 - sb) + ks * 32);
            a0[1] = *(uint32_t*)(sm + (aP0 - sb) + 8 * 272 + ks * 32);
            a0[2] = *(uint32_t*)(sm + (aP0 - sb) + 16 + ks * 32);
            a0[3] = *(uint32_t*)(sm + (aP0 - sb) + 8 * 272 + 16 + ks * 32);
            a1[0] = *(uint32_t*)(sm + (aP1 - sb) + ks * 32);
            a1[1] = *(uint32_t*)(sm + (aP1 - sb) + 8 * 272 + ks * 32);
            a1[2] = *(uint32_t*)(sm + (aP1 - sb) + 16 + ks * 32);
            a1[3] = *(uint32_t*)(sm + (aP1 - sb) + 8 * 272 + 16 + ks * 32);
            uint32_t vb = (bV - sb) + ks * 8 * 1056;
            #pragma unroll
            for (int nt = 0; nt < 16; nt++) {
                uint32_t bb[2];
                bb[0] = *(uint32_t*)(sm + vb + nt * 32);
                bb[1] = *(uint32_t*)(sm + vb + 4 * 1056 + nt * 32);
                mma_tf32(oacc[0][nt], a0, bb);
                mma_tf32(oacc[1][nt], a1, bb);
            }
        }
    }

    // ---- li reduction (4 rows per thread) ----
    li00 += __shfl_xor_sync(0xFFFFFFFFu, li00, 1);
    li00 += __shfl_xor_sync(0xFFFFFFFFu, li00, 2);
    li01 += __shfl_xor_sync(0xFFFFFFFFu, li01, 1);
    li01 += __shfl_xor_sync(0xFFFFFFFFu, li01, 2);
    li10 += __shfl_xor_sync(0xFFFFFFFFu, li10, 1);
    li10 += __shfl_xor_sync(0xFFFFFFFFu, li10, 2);
    li11 += __shfl_xor_sync(0xFFFFFFFFu, li11, 1);
    li11 += __shfl_xor_sync(0xFFFFFFFFu, li11, 2);
    if ((t & 3) == 0) {
        atomicAdd((float*)(sm + ALOFF + r0 * 4), li00);
        atomicAdd((float*)(sm + ALOFF + (r0 + 8) * 4), li01);
        atomicAdd((float*)(sm + ALOFF + (r0 + 16) * 4), li10);
        atomicAdd((float*)(sm + ALOFF + (r0 + 24) * 4), li11);
    }
    __syncthreads();

    // ---- epilogue: O[r][d]/li -> out[d*HW + q0 + r] ----
    float rl00 = 1.0f / *(float*)(sm + ALOFF + r0 * 4);
    float rl01 = 1.0f / *(float*)(sm + ALOFF + (r0 + 8) * 4);
    float rl10 = 1.0f / *(float*)(sm + ALOFF + (r0 + 16) * 4);
    float rl11 = 1.0f / *(float*)(sm + ALOFF + (r0 + 24) * 4);
    #pragma unroll
    for (int nt = 0; nt < 16; nt++) {
        int col = nd0 + nt * 8 + (t & 3) * 2;
        O[col * HW + q0 + r0]            = oacc[0][nt][0] * rl00;
        O[(col + 1) * HW + q0 + r0]      = oacc[0][nt][1] * rl00;
        O[col * HW + q0 + r0 + 8]        = oacc[0][nt][2] * rl01;
        O[(col + 1) * HW + q0 + r0 + 8]  = oacc[0][nt][3] * rl01;
        O[col * HW + q0 + r0 + 16]       = oacc[1][nt][0] * rl10;
        O[(col + 1) * HW + q0 + r0 + 16] = oacc[1][nt][1] * rl10;
        O[col * HW + q0 + r0 + 24]       = oacc[1][nt][2] * rl11;
        O[(col + 1) * HW + q0 + r0 + 24] = oacc[1][nt][3] * rl11;
    }
}

extern "C" void kernel_launch(void* const* d_in, const int* in_sizes, int n_in,
                              void* d_out, int out_size)
{
    const float* fea_left  = (const float*)d_in[0];
    const float* fea_right = (const float*)d_in[1];
    const float* Wq    = (const float*)d_in[2];
    const float* bq    = (const float*)d_in[3];
    const float* gq    = (const float*)d_in[4];
    const float* betaq = (const float*)d_in[5];
    const float* mq    = (const float*)d_in[6];
    const float* vq    = (const float*)d_in[7];
    const float* Wk    = (const float*)d_in[8];
    const float* bk    = (const float*)d_in[9];
    const float* gk    = (const float*)d_in[10];
    const float* betak = (const float*)d_in[11];
    const float* mk    = (const float*)d_in[12];
    const float* vk    = (const float*)d_in[13];
    float* out = (float*)d_out;

    fold_kernel<<<256, 256>>>(Wq, bq, gq, betaq, mq, vq, Wk, bk, gk, betak, mk, vk);
    vconv_kernel<<<(Bsz * CHW / 4 + 255) / 256, 256>>>(fea_left, fea_right);

    cudaFuncSetAttribute(proj_kernel, cudaFuncAttributeMaxDynamicSharedMemorySize, PJ_SMEM);
    proj_kernel<<<dim3(18, 2, 32), 256, PJ_SMEM>>>(fea_left, fea_right);

    cudaFuncSetAttribute(attn_kernel, cudaFuncAttributeMaxDynamicSharedMemorySize, ATT_SMEM);
    attn_kernel<<<dim3(18, 16), 256, ATT_SMEM>>>(out);
}

// round 11
// speedup vs baseline: 9.4541x; 1.4657x over previous
#include <cuda_runtime.h>
#include <cuda_fp16.h>
#include <cstdint>
#include <math.h>

#define Bsz 8
#define Cdim 256
#define HW 2304
#define CHW (Cdim*HW)          // 589824
#define BNEPS 1e-5f
#define INV_C (1.0f/256.0f)

// ---- static scratch (allocation-free), all fp16 ----
__device__ __half g_QhL[Bsz*CHW];
__device__ __half g_QhR[Bsz*CHW];
__device__ __half g_KhL[Bsz*CHW];
__device__ __half g_KhR[Bsz*CHW];
__device__ __half g_VhL[Bsz*CHW];
__device__ __half g_VhR[Bsz*CHW];
__device__ float g_WfQ[Cdim*Cdim];
__device__ float g_WfK[Cdim*Cdim];
__device__ float g_bfQ[Cdim];
__device__ float g_bfK[Cdim];

// ============================================================
// helpers
// ============================================================
__device__ __forceinline__ uint32_t smem_u32(const void* p) {
    uint32_t a;
    asm("{ .reg .u64 t; cvta.to.shared.u64 t, %1; cvt.u32.u64 %0, t; }" : "=r"(a) : "l"(p));
    return a;
}
__device__ __forceinline__ void ldsm_x4(uint32_t a, uint32_t& r0, uint32_t& r1, uint32_t& r2, uint32_t& r3) {
    asm volatile("ldmatrix.sync.aligned.m8n8.x4.shared.b16 {%0,%1,%2,%3}, [%4];"
                 : "=r"(r0), "=r"(r1), "=r"(r2), "=r"(r3) : "r"(a));
}
__device__ __forceinline__ void ldsm_x2(uint32_t a, uint32_t& r0, uint32_t& r1) {
    asm volatile("ldmatrix.sync.aligned.m8n8.x2.shared.b16 {%0,%1}, [%2];"
                 : "=r"(r0), "=r"(r1) : "r"(a));
}
__device__ __forceinline__ void ldsm_x2t(uint32_t a, uint32_t& r0, uint32_t& r1) {
    asm volatile("ldmatrix.sync.aligned.m8n8.x2.trans.shared.b16 {%0,%1}, [%2];"
                 : "=r"(r0), "=r"(r1) : "r"(a));
}
__device__ __forceinline__ void mma_f16(float* c, const uint32_t* a, const uint32_t* b) {
    asm volatile("mma.sync.aligned.m16n8k16.row.col.f32.f16.f16.f32 "
                 "{%0,%1,%2,%3}, {%4,%5,%6,%7}, {%8,%9}, {%0,%1,%2,%3};"
                 : "+f"(c[0]), "+f"(c[1]), "+f"(c[2]), "+f"(c[3])
                 : "r"(a[0]), "r"(a[1]), "r"(a[2]), "r"(a[3]), "r"(b[0]), "r"(b[1]));
}
__device__ __forceinline__ uint32_t pack2h(float a, float b) {
    __half2 t = __floats2half2_rn(a, b);
    return *(uint32_t*)&t;
}
#define CP_ASYNC16(dst, src) \
    asm volatile("cp.async.cg.shared.global [%0], [%1], 16;" :: "r"(dst), "l"(src) : "memory")
#define CP_COMMIT() asm volatile("cp.async.commit_group;" ::: "memory")
#define CP_WAIT0()  asm volatile("cp.async.wait_group 0;" ::: "memory")

// ============================================================
// Fold BN into conv1x1
// ============================================================
__global__ void fold_kernel(const float* __restrict__ Wq, const float* __restrict__ bq,
                            const float* __restrict__ gq, const float* __restrict__ betaq,
                            const float* __restrict__ mq, const float* __restrict__ vq,
                            const float* __restrict__ Wk, const float* __restrict__ bk,
                            const float* __restrict__ gk, const float* __restrict__ betak,
                            const float* __restrict__ mk, const float* __restrict__ vk)
{
    int idx = blockIdx.x * blockDim.x + threadIdx.x;
    if (idx >= Cdim * Cdim) return;
    int o = idx >> 8;
    float sq = gq[o] * rsqrtf(vq[o] + BNEPS);
    float sk = gk[o] * rsqrtf(vk[o] + BNEPS);
    g_WfQ[idx] = Wq[idx] * sq;
    g_WfK[idx] = Wk[idx] * sk;
    if ((idx & 255) == 0) {
        g_bfQ[o] = (bq[o] - mq[o]) * sq + betaq[o];
        g_bfK[o] = (bk[o] - mk[o]) * sk + betak[o];
    }
}

// ============================================================
// V convert: fea fp32 -> fp16 scratch (both sides)
// ============================================================
__global__ void vconv_kernel(const float* __restrict__ fleft, const float* __restrict__ fright)
{
    int i = blockIdx.x * blockDim.x + threadIdx.x;      // float4 index
    const int n4 = (Bsz * CHW) / 4;
    if (i >= n4) return;
    float4 a = ((const float4*)fleft)[i];
    float4 b = ((const float4*)fright)[i];
    ((uint2*)g_VhL)[i] = make_uint2(pack2h(a.x, a.y), pack2h(a.z, a.w));
    ((uint2*)g_VhR)[i] = make_uint2(pack2h(b.x, b.y), pack2h(b.z, b.w));
}

// ============================================================
// Projection GEMM via fp16 mma: dst[o][n] = sum_c Wf[o][c] X[c][n] + bf[o]
// grid (18 n-tiles, 2 o-tiles, 32 = p*8+b), 256 threads (8 warps). fp16 out.
// ============================================================
#define PJ_WOFF 0
#define PJ_XOFF 67584
#define PJ_SMEM (67584 + 32*272)

__global__ void __launch_bounds__(256, 2)
proj_kernel(const float* __restrict__ fleft, const float* __restrict__ fright)
{
    extern __shared__ char sm[];
    uint32_t sb = smem_u32(sm);
    int tid = threadIdx.x;
    int t = tid & 31, w = tid >> 5;

    int z = blockIdx.z;
    int p = z >> 3, b = z & 7;
    const float* X  = ((p & 1) ? fright : fleft) + b * CHW;
    const float* Wf = (p < 2) ? g_WfQ : g_WfK;
    const float* bf = (p < 2) ? g_bfQ : g_bfK;
    __half* dst =
        ((p == 0) ? g_QhL : (p == 1) ? g_QhR : (p == 2) ? g_KhL : g_KhR) + b * CHW;

    int n0 = blockIdx.x * 128, o0 = blockIdx.y * 128;

    #pragma unroll
    for (int it = 0; it < 32; it++) {
        int idx = tid + it * 256;
        int r = idx >> 6, c4 = idx & 63;
        float4 v = *(const float4*)(Wf + (o0 + r) * 256 + c4 * 4);
        *(uint2*)(sm + PJ_WOFF + r * 528 + c4 * 8) = make_uint2(pack2h(v.x, v.y), pack2h(v.z, v.w));
    }

    float oacc[16][4];
    #pragma unroll
    for (int i = 0; i < 16; i++)
        #pragma unroll
        for (int j = 0; j < 4; j++) oacc[i][j] = 0.0f;

    uint32_t aW = sb + PJ_WOFF + (w * 16 + (t & 7) + ((t >> 3) & 1) * 8) * 528 + (t >> 4) * 16;
    uint32_t bX = sb + PJ_XOFF + (t & 15) * 272;

    #pragma unroll 1
    for (int ch = 0; ch < 8; ch++) {
        __syncthreads();
        #pragma unroll
        for (int it = 0; it < 4; it++) {
            int idx = tid + it * 256;
            int rc = idx >> 5, n4 = idx & 31;
            float4 v = *(const float4*)(X + (ch * 32 + rc) * HW + n0 + n4 * 4);
            *(uint2*)(sm + PJ_XOFF + rc * 272 + n4 * 8) = make_uint2(pack2h(v.x, v.y), pack2h(v.z, v.w));
        }
        __syncthreads();

        #pragma unroll
        for (int ksl = 0; ksl < 2; ksl++) {
            uint32_t a[4];
            ldsm_x4(aW + ch * 64 + ksl * 32, a[0], a[1], a[2], a[3]);
            #pragma unroll
            for (int nt = 0; nt < 16; nt++) {
                uint32_t bb[2];
                ldsm_x2t(bX + ksl * 16 * 272 + nt * 16, bb[0], bb[1]);
                mma_f16(oacc[nt], a, bb);
            }
        }
    }

    int r0 = o0 + w * 16 + (t >> 2);
    float b0 = bf[r0], b1 = bf[r0 + 8];
    #pragma unroll
    for (int nt = 0; nt < 16; nt++) {
        int col = n0 + nt * 8 + (t & 3) * 2;
        *(uint32_t*)(dst + r0 * HW + col)       = pack2h(oacc[nt][0] + b0, oacc[nt][1] + b0);
        *(uint32_t*)(dst + (r0 + 8) * HW + col) = pack2h(oacc[nt][2] + b1, oacc[nt][3] + b1);
    }
}

// ============================================================
// Flash attention, all-fp16 operands, fp32 accum.
// 128 q-rows/CTA, 36 key tiles of 64. 256 threads = 8 warps:
// g = w>>1 owns 32 rows (2 A-frags), h = w&1 (32-key half for S, 128-d half for PV).
// smem: Qs[128][528B] | Ks[2][64][528B] | Vs[2][64][528B] | Ps fp16[128][144B] | li[128]
// ============================================================
#define AQOFF 0
#define AKOFF 67584
#define AVOFF 135168
#define APOFF 202752
#define ALOFF 221184
#define ATT_SMEM 221696
#define KVT 33792            // 64*528

__global__ void __launch_bounds__(256, 1)
attn_kernel(float* __restrict__ out)
{
    extern __shared__ char sm[];
    uint32_t sb = smem_u32(sm);
    int tid = threadIdx.x;
    int t = tid & 31, w = tid >> 5;
    int g = w >> 1, h = w & 1;

    int u = blockIdx.y;
    int att = u >> 3, b = u & 7;
    const __half* Q = (att == 0 ? g_QhL : g_QhR) + b * CHW;
    const __half* K = (att == 0 ? g_KhR : g_KhL) + b * CHW;
    const __half* V = (att == 0 ? g_VhR : g_VhL) + b * CHW;
    float* O = out + att * (Bsz * CHW) + b * CHW;
    int q0 = blockIdx.x * 128;

    if (tid < 128) *(float*)(sm + ALOFF + tid * 4) = 0.0f;

    // Q tile via cp.async: 128 rows x 32 chunks of 16B
    #pragma unroll
    for (int it = 0; it < 16; it++) {
        int idx = tid + it * 256;
        int r = idx >> 5, c16 = idx & 31;
        CP_ASYNC16(sb + AQOFF + r * 528 + c16 * 16, (const char*)(Q + (q0 + r) * 256) + c16 * 16);
    }
    // K/V tile 0 into buffer 0 (64 rows x 32 chunks each)
    #pragma unroll
    for (int it = 0; it < 8; it++) {
        int idx = tid + it * 256;
        int r = idx >> 5, c16 = idx & 31;
        CP_ASYNC16(sb + AKOFF + r * 528 + c16 * 16, (const char*)(K + r * 256) + c16 * 16);
        CP_ASYNC16(sb + AVOFF + r * 528 + c16 * 16, (const char*)(V + r * 256) + c16 * 16);
    }
    CP_COMMIT();

    int m0 = g * 32;            // 32-row group
    int n0 = h * 32;            // 32-key half (S phase)
    int nd0 = h * 128;          // 128-d half (PV phase)

    uint32_t aQ0 = sb + AQOFF + (m0 + (t & 7) + ((t >> 3) & 1) * 8) * 528 + (t >> 4) * 16;
    uint32_t aQ1 = aQ0 + 16 * 528;
    int r0 = m0 + (t >> 2);
    uint32_t aP0 = sb + APOFF + (m0 + (t & 7) + ((t >> 3) & 1) * 8) * 144 + (t >> 4) * 16;
    uint32_t aP1 = aP0 + 16 * 144;

    float oacc[2][16][4];
    #pragma unroll
    for (int f = 0; f < 2; f++)
        #pragma unroll
        for (int i = 0; i < 16; i++)
            #pragma unroll
            for (int j = 0; j < 4; j++) oacc[f][i][j] = 0.0f;
    float li00 = 0.0f, li01 = 0.0f, li10 = 0.0f, li11 = 0.0f;

    #pragma unroll 1
    for (int kt = 0; kt < 36; kt++) {
        int buf = kt & 1;
        uint32_t kbase = sb + AKOFF + buf * KVT;
        uint32_t vbase = sb + AVOFF + buf * KVT;

        CP_WAIT0();
        __syncthreads();      // tile kt resident; prev iter's P/V consumers done

        // prefetch tile kt+1 into other buffer
        if (kt < 35) {
            int k0n = (kt + 1) * 64;
            uint32_t kd = sb + AKOFF + (buf ^ 1) * KVT;
            uint32_t vd = sb + AVOFF + (buf ^ 1) * KVT;
            #pragma unroll
            for (int it = 0; it < 8; it++) {
                int idx = tid + it * 256;
                int r = idx >> 5, c16 = idx & 31;
                CP_ASYNC16(kd + r * 528 + c16 * 16, (const char*)(K + (k0n + r) * 256) + c16 * 16);
                CP_ASYNC16(vd + r * 528 + c16 * 16, (const char*)(V + (k0n + r) * 256) + c16 * 16);
            }
            CP_COMMIT();
        }

        // ---- S = Q K^T (fp16): warp computes S[32 x 32] via 2 A-frags ----
        uint32_t bK = kbase + (n0 + (t & 7)) * 528 + ((t >> 3) & 1) * 16;
        float sacc[2][4][4];
        #pragma unroll
        for (int f = 0; f < 2; f++)
            #pragma unroll
            for (int i = 0; i < 4; i++)
                #pragma unroll
                for (int j = 0; j < 4; j++) sacc[f][i][j] = 0.0f;
        #pragma unroll
        for (int ks = 0; ks < 16; ks++) {
            uint32_t a0[4], a1[4];
            ldsm_x4(aQ0 + ks * 32, a0[0], a0[1], a0[2], a0[3]);
            ldsm_x4(aQ1 + ks * 32, a1[0], a1[1], a1[2], a1[3]);
            #pragma unroll
            for (int nt = 0; nt < 4; nt++) {
                uint32_t bb[2];
                ldsm_x2(bK + nt * 8 * 528 + ks * 32, bb[0], bb[1]);
                mma_f16(sacc[0][nt], a0, bb);
                mma_f16(sacc[1][nt], a1, bb);
            }
        }

        // ---- softmax (no max subtraction) + store P (fp16) ----
        #pragma unroll
        for (int f = 0; f < 2; f++) {
            int rf = r0 + f * 16;
            #pragma unroll
            for (int nt = 0; nt < 4; nt++) {
                float p0 = __expf(sacc[f][nt][0] * INV_C);
                float p1 = __expf(sacc[f][nt][1] * INV_C);
                float p2 = __expf(sacc[f][nt][2] * INV_C);
                float p3 = __expf(sacc[f][nt][3] * INV_C);
                if (f == 0) { li00 += p0 + p1; li01 += p2 + p3; }
                else        { li10 += p0 + p1; li11 += p2 + p3; }
                int col = n0 + nt * 8 + (t & 3) * 2;
                *(uint32_t*)(sm + APOFF + rf * 144 + col * 2)       = pack2h(p0, p1);
                *(uint32_t*)(sm + APOFF + (rf + 8) * 144 + col * 2) = pack2h(p2, p3);
            }
        }
        __syncthreads();   // P complete

        // ---- O += P @ V (fp16): each V B-frag feeds both A-frags ----
        uint32_t bV = vbase + (t & 15) * 528 + nd0 * 2;
        #pragma unroll
        for (int ks = 0; ks < 4; ks++) {
            uint32_t a0[4], a1[4];
            ldsm_x4(aP0 + ks * 32, a0[0], a0[1], a0[2], a0[3]);
            ldsm_x4(aP1 + ks * 32, a1[0], a1[1], a1[2], a1[3]);
            #pragma unroll
            for (int nt = 0; nt < 16; nt++) {
                uint32_t bb[2];
                ldsm_x2t(bV + ks * 16 * 528 + nt * 16, bb[0], bb[1]);
                mma_f16(oacc[0][nt], a0, bb);
                mma_f16(oacc[1][nt], a1, bb);
            }
        }
    }

    // ---- li reduction (4 rows per thread) ----
    li00 += __shfl_xor_sync(0xFFFFFFFFu, li00, 1);
    li00 += __shfl_xor_sync(0xFFFFFFFFu, li00, 2);
    li01 += __shfl_xor_sync(0xFFFFFFFFu, li01, 1);
    li01 += __shfl_xor_sync(0xFFFFFFFFu, li01, 2);
    li10 += __shfl_xor_sync(0xFFFFFFFFu, li10, 1);
    li10 += __shfl_xor_sync(0xFFFFFFFFu, li10, 2);
    li11 += __shfl_xor_sync(0xFFFFFFFFu, li11, 1);
    li11 += __shfl_xor_sync(0xFFFFFFFFu, li11, 2);
    if ((t & 3) == 0) {
        atomicAdd((float*)(sm + ALOFF + r0 * 4), li00);
        atomicAdd((float*)(sm + ALOFF + (r0 + 8) * 4), li01);
        atomicAdd((float*)(sm + ALOFF + (r0 + 16) * 4), li10);
        atomicAdd((float*)(sm + ALOFF + (r0 + 24) * 4), li11);
    }
    __syncthreads();

    // ---- epilogue: O[r][d]/li -> out[d*HW + q0 + r] ----
    float rl00 = 1.0f / *(float*)(sm + ALOFF + r0 * 4);
    float rl01 = 1.0f / *(float*)(sm + ALOFF + (r0 + 8) * 4);
    float rl10 = 1.0f / *(float*)(sm + ALOFF + (r0 + 16) * 4);
    float rl11 = 1.0f / *(float*)(sm + ALOFF + (r0 + 24) * 4);
    #pragma unroll
    for (int nt = 0; nt < 16; nt++) {
        int col = nd0 + nt * 8 + (t & 3) * 2;
        O[col * HW + q0 + r0]            = oacc[0][nt][0] * rl00;
        O[(col + 1) * HW + q0 + r0]      = oacc[0][nt][1] * rl00;
        O[col * HW + q0 + r0 + 8]        = oacc[0][nt][2] * rl01;
        O[(col + 1) * HW + q0 + r0 + 8]  = oacc[0][nt][3] * rl01;
        O[col * HW + q0 + r0 + 16]       = oacc[1][nt][0] * rl10;
        O[(col + 1) * HW + q0 + r0 + 16] = oacc[1][nt][1] * rl10;
        O[col * HW + q0 + r0 + 24]       = oacc[1][nt][2] * rl11;
        O[(col + 1) * HW + q0 + r0 + 24] = oacc[1][nt][3] * rl11;
    }
}

extern "C" void kernel_launch(void* const* d_in, const int* in_sizes, int n_in,
                              void* d_out, int out_size)
{
    const float* fea_left  = (const float*)d_in[0];
    const float* fea_right = (const float*)d_in[1];
    const float* Wq    = (const float*)d_in[2];
    const float* bq    = (const float*)d_in[3];
    const float* gq    = (const float*)d_in[4];
    const float* betaq = (const float*)d_in[5];
    const float* mq    = (const float*)d_in[6];
    const float* vq    = (const float*)d_in[7];
    const float* Wk    = (const float*)d_in[8];
    const float* bk    = (const float*)d_in[9];
    const float* gk    = (const float*)d_in[10];
    const float* betak = (const float*)d_in[11];
    const float* mk    = (const float*)d_in[12];
    const float* vk    = (const float*)d_in[13];
    float* out = (float*)d_out;

    fold_kernel<<<256, 256>>>(Wq, bq, gq, betaq, mq, vq, Wk, bk, gk, betak, mk, vk);
    vconv_kernel<<<(Bsz * CHW / 4 + 255) / 256, 256>>>(fea_left, fea_right);

    cudaFuncSetAttribute(proj_kernel, cudaFuncAttributeMaxDynamicSharedMemorySize, PJ_SMEM);
    proj_kernel<<<dim3(18, 2, 32), 256, PJ_SMEM>>>(fea_left, fea_right);

    cudaFuncSetAttribute(attn_kernel, cudaFuncAttributeMaxDynamicSharedMemorySize, ATT_SMEM);
    attn_kernel<<<dim3(18, 16), 256, ATT_SMEM>>>(out);
}